// round 2
// baseline (speedup 1.0000x reference)
#include <cuda_runtime.h>
#include <math.h>

#define B_   8
#define P_   128
#define N_   256
#define D_   128
#define DIN_ 256
#define M_   (B_*P_*N_)        // 262144 rows
#define ROWSTRIDE_ (N_*D_)     // 32768 floats between consecutive p for fixed (b,n)

// ---------------- scratch (device globals; no allocation allowed) ----------------
__device__ float g_q[(size_t)M_ * D_];
__device__ float g_k[(size_t)M_ * D_];
__device__ float g_v[(size_t)M_ * D_];
__device__ float g_att[(size_t)M_ * D_];

__device__ __forceinline__ const float* resolve_in(const float* ext, int sel) {
    switch (sel) {
        case 0: return g_q;
        case 1: return g_k;
        case 2: return g_v;
        case 3: return g_att;
        default: return ext;
    }
}
__device__ __forceinline__ float* resolve_out(float* ext, int sel) {
    switch (sel) {
        case 0: return g_q;
        case 1: return g_k;
        case 2: return g_v;
        case 3: return g_att;
        default: return ext;
    }
}

// ---------------- SGEMM: C[M x 128] = act(A[M x KDIM] @ W[KDIM x 128] + bias) ----
// Tile: 128x128 per block, 256 threads, 8x8 microtile, BK=16.
// CONCAT: A columns [0,128) come from A, [128,256) from A2 (both row-stride 128).
template<int KDIM, bool RELU, bool CONCAT>
__global__ __launch_bounds__(256, 2)
void gemm_kernel(const float* __restrict__ Aext, const float* __restrict__ A2,
                 const float* __restrict__ W, const float* __restrict__ bias,
                 float* __restrict__ Oext, int asel, int osel)
{
    const float* A = resolve_in(Aext, asel);
    float* out = resolve_out(Oext, osel);

    __shared__ float As[16][132];   // transposed A tile: As[k][row]
    __shared__ float Bs[16][132];   // W tile: Bs[k][col]

    const int tid = threadIdx.x;          // 0..255
    const int tx = tid & 15;              // col group
    const int ty = tid >> 4;              // row group
    const int row0 = blockIdx.x * 128;

    float acc[8][8];
#pragma unroll
    for (int i = 0; i < 8; i++)
#pragma unroll
        for (int j = 0; j < 8; j++) acc[i][j] = 0.f;

    for (int kt = 0; kt < KDIM; kt += 16) {
        const float* Asrc = A;
        int kb = kt;
        if (CONCAT && kt >= 128) { Asrc = A2; kb = kt - 128; }

        // load A tile: 128 rows x 16 k  (512 float4, 2 per thread), transpose into As
#pragma unroll
        for (int l = 0; l < 2; l++) {
            int id = tid * 2 + l;             // 0..511
            int r  = id >> 2;                 // 0..127
            int k4 = (id & 3) << 2;           // 0,4,8,12
            float4 v = *(const float4*)(Asrc + (size_t)(row0 + r) * 128 + kb + k4);
            As[k4 + 0][r] = v.x;
            As[k4 + 1][r] = v.y;
            As[k4 + 2][r] = v.z;
            As[k4 + 3][r] = v.w;
        }
        // load W tile: 16 k x 128 cols (512 float4, 2 per thread)
#pragma unroll
        for (int l = 0; l < 2; l++) {
            int id = tid * 2 + l;             // 0..511
            int kk = id >> 5;                 // 0..15
            int j4 = (id & 31) << 2;          // 0..124
            *(float4*)&Bs[kk][j4] = *(const float4*)(W + (size_t)(kt + kk) * 128 + j4);
        }
        __syncthreads();

#pragma unroll
        for (int kk = 0; kk < 16; kk++) {
            float a[8], b[8];
            *(float4*)&a[0] = *(float4*)&As[kk][ty * 8];
            *(float4*)&a[4] = *(float4*)&As[kk][ty * 8 + 4];
            *(float4*)&b[0] = *(float4*)&Bs[kk][tx * 8];
            *(float4*)&b[4] = *(float4*)&Bs[kk][tx * 8 + 4];
#pragma unroll
            for (int i = 0; i < 8; i++)
#pragma unroll
                for (int j = 0; j < 8; j++)
                    acc[i][j] = fmaf(a[i], b[j], acc[i][j]);
        }
        __syncthreads();
    }

    // epilogue: bias (+relu), vectorized store
    float bv[8];
#pragma unroll
    for (int j = 0; j < 8; j++) bv[j] = bias[tx * 8 + j];

#pragma unroll
    for (int i = 0; i < 8; i++) {
        int row = row0 + ty * 8 + i;
        float r[8];
#pragma unroll
        for (int j = 0; j < 8; j++) {
            float s = acc[i][j] + bv[j];
            if (RELU) s = fmaxf(s, 0.f);
            r[j] = s;
        }
        *(float4*)(out + (size_t)row * 128 + tx * 8)     = make_float4(r[0], r[1], r[2], r[3]);
        *(float4*)(out + (size_t)row * 128 + tx * 8 + 4) = make_float4(r[4], r[5], r[6], r[7]);
    }
}

// ---------------- attention: one block per (b, head, node) ----------------------
// thread t == query time index p. K/V staged in shared, Q row in registers,
// single-pass online softmax (causal: q <= p). Masked entries in the reference
// get weight exp(-65504 - m) == 0 in fp32, so skipping them is exact.
__global__ __launch_bounds__(128)
void attn_kernel()
{
    const int n  = blockIdx.x;        // 0..255
    const int bh = blockIdx.y;        // 0..63
    const int b  = bh >> 3;
    const int h  = bh & 7;
    const int t  = threadIdx.x;       // query time p, 0..127

    __shared__ float Ks[128][16];
    __shared__ float Vs[128][16];

    // base offset of (b, p=0, n) row, at this head's slice
    const size_t base = ((size_t)(b * P_) * N_ + n) * D_ + h * 16;

    // cooperative K/V load: 128 rows x 16 floats each = 512 float4 per tensor
#pragma unroll
    for (int i = 0; i < 4; i++) {
        int id = t + i * 128;          // 0..511
        int r  = id >> 2;              // key time index
        int d4 = (id & 3) << 2;        // 0,4,8,12
        size_t g = base + (size_t)r * ROWSTRIDE_ + d4;
        *(float4*)&Ks[r][d4] = *(const float4*)&g_k[g];
        *(float4*)&Vs[r][d4] = *(const float4*)&g_v[g];
    }

    // Q row for this thread
    float qr[16];
#pragma unroll
    for (int d4 = 0; d4 < 16; d4 += 4) {
        float4 v = *(const float4*)&g_q[base + (size_t)t * ROWSTRIDE_ + d4];
        qr[d4 + 0] = v.x; qr[d4 + 1] = v.y; qr[d4 + 2] = v.z; qr[d4 + 3] = v.w;
    }
    __syncthreads();

    float m = -1e30f, denom = 0.f;
    float o[16];
#pragma unroll
    for (int d = 0; d < 16; d++) o[d] = 0.f;

    for (int q = 0; q <= t; q++) {
        float4 k0 = *(const float4*)&Ks[q][0];
        float4 k1 = *(const float4*)&Ks[q][4];
        float4 k2 = *(const float4*)&Ks[q][8];
        float4 k3 = *(const float4*)&Ks[q][12];
        float s = qr[0] * k0.x;
        s = fmaf(qr[1],  k0.y, s); s = fmaf(qr[2],  k0.z, s); s = fmaf(qr[3],  k0.w, s);
        s = fmaf(qr[4],  k1.x, s); s = fmaf(qr[5],  k1.y, s); s = fmaf(qr[6],  k1.z, s); s = fmaf(qr[7],  k1.w, s);
        s = fmaf(qr[8],  k2.x, s); s = fmaf(qr[9],  k2.y, s); s = fmaf(qr[10], k2.z, s); s = fmaf(qr[11], k2.w, s);
        s = fmaf(qr[12], k3.x, s); s = fmaf(qr[13], k3.y, s); s = fmaf(qr[14], k3.z, s); s = fmaf(qr[15], k3.w, s);
        s *= 0.25f;   // 1/sqrt(d_head=16)

        if (s > m) {
            float scale = __expf(m - s);
            denom *= scale;
#pragma unroll
            for (int d = 0; d < 16; d++) o[d] *= scale;
            m = s;
        }
        float w = __expf(s - m);
        denom += w;

        float4 v0 = *(const float4*)&Vs[q][0];
        float4 v1 = *(const float4*)&Vs[q][4];
        float4 v2 = *(const float4*)&Vs[q][8];
        float4 v3 = *(const float4*)&Vs[q][12];
        o[0]  = fmaf(w, v0.x, o[0]);  o[1]  = fmaf(w, v0.y, o[1]);
        o[2]  = fmaf(w, v0.z, o[2]);  o[3]  = fmaf(w, v0.w, o[3]);
        o[4]  = fmaf(w, v1.x, o[4]);  o[5]  = fmaf(w, v1.y, o[5]);
        o[6]  = fmaf(w, v1.z, o[6]);  o[7]  = fmaf(w, v1.w, o[7]);
        o[8]  = fmaf(w, v2.x, o[8]);  o[9]  = fmaf(w, v2.y, o[9]);
        o[10] = fmaf(w, v2.z, o[10]); o[11] = fmaf(w, v2.w, o[11]);
        o[12] = fmaf(w, v3.x, o[12]); o[13] = fmaf(w, v3.y, o[13]);
        o[14] = fmaf(w, v3.z, o[14]); o[15] = fmaf(w, v3.w, o[15]);
    }

    float inv = 1.f / denom;
    size_t ob = base + (size_t)t * ROWSTRIDE_;
    *(float4*)&g_att[ob + 0]  = make_float4(o[0] * inv,  o[1] * inv,  o[2] * inv,  o[3] * inv);
    *(float4*)&g_att[ob + 4]  = make_float4(o[4] * inv,  o[5] * inv,  o[6] * inv,  o[7] * inv);
    *(float4*)&g_att[ob + 8]  = make_float4(o[8] * inv,  o[9] * inv,  o[10] * inv, o[11] * inv);
    *(float4*)&g_att[ob + 12] = make_float4(o[12] * inv, o[13] * inv, o[14] * inv, o[15] * inv);
}

// ---------------- launch -------------------------------------------------------
extern "C" void kernel_launch(void* const* d_in, const int* in_sizes, int n_in,
                              void* d_out, int out_size)
{
    const float* X   = (const float*)d_in[0];
    const float* STE = (const float*)d_in[1];
    const float* Wq  = (const float*)d_in[2];
    const float* bq  = (const float*)d_in[3];
    const float* Wk  = (const float*)d_in[4];
    const float* bk  = (const float*)d_in[5];
    const float* Wv  = (const float*)d_in[6];
    const float* bv  = (const float*)d_in[7];
    const float* W1  = (const float*)d_in[8];
    const float* b1  = (const float*)d_in[9];
    const float* W2  = (const float*)d_in[10];
    const float* b2  = (const float*)d_in[11];
    float* out = (float*)d_out;

    const int nblk = M_ / 128;   // 2048

    // QKV projections: C = relu(concat(X,STE) @ W + b)
    gemm_kernel<256, true, true><<<nblk, 256>>>(X, STE, Wq, bq, nullptr, -1, 0);
    gemm_kernel<256, true, true><<<nblk, 256>>>(X, STE, Wk, bk, nullptr, -1, 1);
    gemm_kernel<256, true, true><<<nblk, 256>>>(X, STE, Wv, bv, nullptr, -1, 2);

    // causal attention per (b, head, node)
    attn_kernel<<<dim3(N_, B_ * 8), 128>>>();

    // output MLP: relu(att @ W1 + b1) @ W2 + b2
    gemm_kernel<128, true,  false><<<nblk, 256>>>(nullptr, nullptr, W1, b1, nullptr, 3, 0);
    gemm_kernel<128, false, false><<<nblk, 256>>>(nullptr, nullptr, W2, b2, out, 0, -1);
}